// round 9
// baseline (speedup 1.0000x reference)
#include <cuda_runtime.h>

#define CEPS 1e-3f

// scratch (allocation-free rule: __device__ globals)
__device__ float g_y0[100000 * 16];
__device__ float g_y0b[100000 * 16];
__device__ float g_y1[100000 * 16];
__device__ float g_merged[200000 * 16];
__device__ float g_stats[64];   // [0:16) sum0, [16:32) sq0, [32:48) sum1, [48:64) sq1
__device__ int   g_nbrT[27 * 100000];

// ---------------------------------------------------------------------------
// Transpose rulebook: nbrT[k*N+n] = nbr[n*27+k]. Block: 256 rows.
// ---------------------------------------------------------------------------
__global__ __launch_bounds__(256) void transpose_nbr_kernel(
    const int* __restrict__ nbr, int N)
{
    __shared__ int t[256 * 27];
    int tid = threadIdx.x;
    int n0 = blockIdx.x * 256;
    int lim = (N - n0) * 27;
    for (int i = tid; i < 256 * 27; i += 256)
        t[i] = (i < lim) ? nbr[n0 * 27 + i] : -1;
    __syncthreads();
    int n = n0 + tid;
    if (n < N) {
#pragma unroll
        for (int k = 0; k < 27; k++)
            g_nbrT[k * N + n] = t[tid * 27 + k];
    }
}

// ---------------------------------------------------------------------------
// Submanifold 3x3x3 conv, register-direct gather, software-pipelined.
// 256 threads -> 128 rows; thread = (row, cout-half): 8 couts, all 16 cins.
// Pipeline: ids prefetched 2 k ahead, x-rows 1 k ahead -> gather latency
// overlaps the previous k's FMA block. Warp-level skip of all-empty offsets.
// ---------------------------------------------------------------------------
__global__ __launch_bounds__(256) void conv_kernel(
    const float* __restrict__ x, const float* __restrict__ W,
    float* __restrict__ y, int N, int statbase)
{
    __shared__ float Ws[27 * 256];   // 27.6 KB [k][c][o]
    __shared__ float sstat[32];

    int tid = threadIdx.x;
    for (int i = tid; i < 27 * 256; i += 256) Ws[i] = W[i];
    if (tid < 32) sstat[tid] = 0.f;
    __syncthreads();

    int half = (tid & 1) * 8;              // cout offset: 0 or 8
    int n    = blockIdx.x * 128 + (tid >> 1);
    bool vn  = (n < N);
    const int* nbrp = g_nbrT + n;

    float4 acc0 = make_float4(0.f, 0.f, 0.f, 0.f);
    float4 acc1 = acc0;

    // pipeline state: id0 = current k, id1 = k+1; v = x-row for id0
    int id0 = vn ? nbrp[0] : -1;
    int id1 = vn ? nbrp[N] : -1;
    float4 v0, v1, v2, v3;
    if (id0 >= 0) {
        const float4* xp = (const float4*)(x + id0 * 16);
        v0 = xp[0]; v1 = xp[1]; v2 = xp[2]; v3 = xp[3];
    } else {
        v0 = v1 = v2 = v3 = make_float4(0.f, 0.f, 0.f, 0.f);
    }

#define CSTEP(xc, cidx) {                                            \
        float4 wa = *(const float4*)(Wk + (cidx) * 16);              \
        float4 wb = *(const float4*)(Wk + (cidx) * 16 + 4);          \
        acc0.x = fmaf(xc, wa.x, acc0.x); acc0.y = fmaf(xc, wa.y, acc0.y); \
        acc0.z = fmaf(xc, wa.z, acc0.z); acc0.w = fmaf(xc, wa.w, acc0.w); \
        acc1.x = fmaf(xc, wb.x, acc1.x); acc1.y = fmaf(xc, wb.y, acc1.y); \
        acc1.z = fmaf(xc, wb.z, acc1.z); acc1.w = fmaf(xc, wb.w, acc1.w); }

#pragma unroll 1
    for (int k = 0; k < 27; k++) {
        // prefetch id for k+2 (no dependency)
        int id2 = (k + 2 < 27 && vn) ? nbrp[(k + 2) * N] : -1;
        // prefetch x-row for k+1 (id1 resolved one iteration ago)
        float4 p0, p1, p2, p3;
        if (id1 >= 0) {
            const float4* xp = (const float4*)(x + id1 * 16);
            p0 = xp[0]; p1 = xp[1]; p2 = xp[2]; p3 = xp[3];
        } else {
            p0 = p1 = p2 = p3 = make_float4(0.f, 0.f, 0.f, 0.f);
        }

        if (__any_sync(0xffffffffu, id0 >= 0)) {
            const float* Wk = Ws + k * 256 + half;
            CSTEP(v0.x, 0)  CSTEP(v0.y, 1)  CSTEP(v0.z, 2)  CSTEP(v0.w, 3)
            CSTEP(v1.x, 4)  CSTEP(v1.y, 5)  CSTEP(v1.z, 6)  CSTEP(v1.w, 7)
            CSTEP(v2.x, 8)  CSTEP(v2.y, 9)  CSTEP(v2.z, 10) CSTEP(v2.w, 11)
            CSTEP(v3.x, 12) CSTEP(v3.y, 13) CSTEP(v3.z, 14) CSTEP(v3.w, 15)
        }
        v0 = p0; v1 = p1; v2 = p2; v3 = p3;
        id0 = id1; id1 = id2;
    }
#undef CSTEP

    if (vn) {
        float4* yp = (float4*)(y + n * 16 + half);
        yp[0] = acc0; yp[1] = acc1;
    }

    // ---- BN stats: parity-preserving butterfly (lanes of same cout-half) ----
    float s[8] = {acc0.x, acc0.y, acc0.z, acc0.w, acc1.x, acc1.y, acc1.z, acc1.w};
    float q[8];
#pragma unroll
    for (int j = 0; j < 8; j++) q[j] = s[j] * s[j];
#pragma unroll
    for (int off = 2; off < 32; off <<= 1) {
#pragma unroll
        for (int j = 0; j < 8; j++) {
            s[j] += __shfl_xor_sync(0xffffffffu, s[j], off);
            q[j] += __shfl_xor_sync(0xffffffffu, q[j], off);
        }
    }
    if ((tid & 31) < 2) {   // lane0: couts 0-7, lane1: couts 8-15
#pragma unroll
        for (int j = 0; j < 8; j++) {
            atomicAdd(&sstat[half + j], s[j]);
            atomicAdd(&sstat[16 + half + j], q[j]);
        }
    }
    __syncthreads();
    if (tid < 32) atomicAdd(&g_stats[statbase + tid], sstat[tid]);
}

// y0b = relu(bn0(y0)) elementwise (affine from g_stats base 0)
__global__ __launch_bounds__(256) void bnrelu_kernel(
    const float* __restrict__ yin, float* __restrict__ yout,
    const float* __restrict__ g, const float* __restrict__ b,
    int N, float invN)
{
    __shared__ float saff[32];
    int tid = threadIdx.x;
    if (tid < 16) {
        float mu  = g_stats[tid] * invN;
        float var = g_stats[16 + tid] * invN - mu * mu;
        float s   = g[tid] * rsqrtf(var + CEPS);
        saff[tid]      = s;
        saff[16 + tid] = b[tid] - mu * s;
    }
    __syncthreads();
    int i = blockIdx.x * 256 + tid;      // one float4 (4 channels) per thread
    if (i >= N * 4) return;
    int c4 = (i & 3) * 4;
    float4 v = *(const float4*)(yin + i * 4);
    v.x = fmaxf(fmaf(v.x, saff[c4 + 0], saff[16 + c4 + 0]), 0.f);
    v.y = fmaxf(fmaf(v.y, saff[c4 + 1], saff[16 + c4 + 1]), 0.f);
    v.z = fmaxf(fmaf(v.z, saff[c4 + 2], saff[16 + c4 + 2]), 0.f);
    v.w = fmaxf(fmaf(v.w, saff[c4 + 3], saff[16 + c4 + 3]), 0.f);
    *(float4*)(yout + i * 4) = v;
}

// tiny stats-zero kernel
__global__ void zero_stats_kernel() {
    if (threadIdx.x < 64) g_stats[threadIdx.x] = 0.f;
}

// t2 = f2 @ Wobo + bobo, atomicAdd-scatter into merged
__global__ __launch_bounds__(256) void fuse_t2_kernel(
    const float* __restrict__ f2, const float* __restrict__ Wobo,
    const float* __restrict__ bobo, const int* __restrict__ seg2, int N)
{
    __shared__ float Wo[256];
    __shared__ float sf[16 * 17];
    __shared__ float sb[16];
    int tid = threadIdx.x;
    Wo[tid] = Wobo[tid];
    if (tid < 16) sb[tid] = bobo[tid];
    int n0 = blockIdx.x * 16;
    if (tid < 64) {
        int r = tid >> 2, c4 = (tid & 3) * 4;
        float4 v = make_float4(0.f, 0.f, 0.f, 0.f);
        if (n0 + r < N) v = *(const float4*)(f2 + (n0 + r) * 16 + c4);
        sf[r * 17 + c4 + 0] = v.x; sf[r * 17 + c4 + 1] = v.y;
        sf[r * 17 + c4 + 2] = v.z; sf[r * 17 + c4 + 3] = v.w;
    }
    __syncthreads();
    int tx = tid & 15, ty = tid >> 4;
    int n = n0 + ty;
    if (n >= N) return;
    float acc = sb[tx];
#pragma unroll
    for (int c = 0; c < 16; c++)
        acc = fmaf(sf[ty * 17 + c], Wo[c * 16 + tx], acc);
    atomicAdd(&g_merged[seg2[n] * 16 + tx], acc);
}

// h = relu(bn1(y1)), atomicAdd-scatter into merged
__global__ __launch_bounds__(256) void fuse_h_kernel(
    const float* __restrict__ y1, const float* __restrict__ g1,
    const float* __restrict__ b1, const int* __restrict__ seg, int N, float invN)
{
    __shared__ float saff[32];
    int tid = threadIdx.x;
    if (tid < 16) {
        float mu  = g_stats[32 + tid] * invN;
        float var = g_stats[48 + tid] * invN - mu * mu;
        float s   = g1[tid] * rsqrtf(var + CEPS);
        saff[tid]      = s;
        saff[16 + tid] = b1[tid] - mu * s;
    }
    __syncthreads();
    int tx = tid & 15, ty = tid >> 4;
    int n = blockIdx.x * 16 + ty;
    if (n >= N) return;
    float h = fmaxf(fmaf(y1[n * 16 + tx], saff[tx], saff[16 + tx]), 0.f);
    atomicAdd(&g_merged[seg[n] * 16 + tx], h);
}

// out[u,:] = merged[u,:] @ Wf + bf.  32 rows x 128 cols per block.
__global__ __launch_bounds__(256) void out_kernel(
    const float* __restrict__ Wf, const float* __restrict__ bf,
    float* __restrict__ out, int U)
{
    __shared__ float Wfs[2048];
    __shared__ float sx[32 * 16];
    int tid = threadIdx.x;
    for (int i = tid; i < 2048; i += 256) Wfs[i] = Wf[i];
    int u0 = blockIdx.x * 32;
    if (tid < 128) {
        int r = tid >> 2, c4 = (tid & 3) * 4;
        float4 v = make_float4(0.f, 0.f, 0.f, 0.f);
        if (u0 + r < U) v = *(const float4*)(g_merged + (u0 + r) * 16 + c4);
        *(float4*)(sx + r * 16 + c4) = v;
    }
    __syncthreads();

    int cx = tid & 31, ry = tid >> 5;
    float4 bv = *(const float4*)(bf + cx * 4);
    float4 a0 = bv, a1 = bv, a2 = bv, a3 = bv;

#pragma unroll
    for (int c = 0; c < 16; c++) {
        float4 wv = *(const float4*)(Wfs + c * 128 + cx * 4);
        float x0 = sx[(ry * 4 + 0) * 16 + c];
        float x1 = sx[(ry * 4 + 1) * 16 + c];
        float x2 = sx[(ry * 4 + 2) * 16 + c];
        float x3 = sx[(ry * 4 + 3) * 16 + c];
        a0.x = fmaf(x0, wv.x, a0.x); a0.y = fmaf(x0, wv.y, a0.y);
        a0.z = fmaf(x0, wv.z, a0.z); a0.w = fmaf(x0, wv.w, a0.w);
        a1.x = fmaf(x1, wv.x, a1.x); a1.y = fmaf(x1, wv.y, a1.y);
        a1.z = fmaf(x1, wv.z, a1.z); a1.w = fmaf(x1, wv.w, a1.w);
        a2.x = fmaf(x2, wv.x, a2.x); a2.y = fmaf(x2, wv.y, a2.y);
        a2.z = fmaf(x2, wv.z, a2.z); a2.w = fmaf(x2, wv.w, a2.w);
        a3.x = fmaf(x3, wv.x, a3.x); a3.y = fmaf(x3, wv.y, a3.y);
        a3.z = fmaf(x3, wv.z, a3.z); a3.w = fmaf(x3, wv.w, a3.w);
    }

    int u = u0 + ry * 4;
    if (u + 0 < U) *(float4*)(out + (u + 0) * 128 + cx * 4) = a0;
    if (u + 1 < U) *(float4*)(out + (u + 1) * 128 + cx * 4) = a1;
    if (u + 2 < U) *(float4*)(out + (u + 2) * 128 + cx * 4) = a2;
    if (u + 3 < U) *(float4*)(out + (u + 3) * 128 + cx * 4) = a3;
}

extern "C" void kernel_launch(void* const* d_in, const int* in_sizes, int n_in,
                              void* d_out, int out_size)
{
    const float* vox  = (const float*)d_in[0];
    const float* f2   = (const float*)d_in[1];
    const float* W0   = (const float*)d_in[2];
    const float* g0   = (const float*)d_in[3];
    const float* b0   = (const float*)d_in[4];
    const float* W1   = (const float*)d_in[5];
    const float* g1   = (const float*)d_in[6];
    const float* b1   = (const float*)d_in[7];
    const float* Wobo = (const float*)d_in[8];
    const float* bobo = (const float*)d_in[9];
    const float* Wf   = (const float*)d_in[10];
    const float* bf   = (const float*)d_in[11];
    const int*   nbr  = (const int*)d_in[12];
    const int*   seg  = (const int*)d_in[13];

    int N = in_sizes[0] / 16;
    int U = out_size / 128;

    void *p_merged, *p_y0, *p_y0b, *p_y1;
    cudaGetSymbolAddress(&p_merged, g_merged);
    cudaGetSymbolAddress(&p_y0,     g_y0);
    cudaGetSymbolAddress(&p_y0b,    g_y0b);
    cudaGetSymbolAddress(&p_y1,     g_y1);

    size_t mbytes = (size_t)U * 16 * sizeof(float);
    size_t mhalf  = (mbytes / 2) & ~(size_t)255;
    float invN = 1.0f / (float)N;
    int tblocks = (N + 255) / 256;
    int cblocks = (N + 127) / 128;

    // launch indices (ncu -s 5 -c 1 profiles index 5 = conv0)
    cudaMemsetAsync(p_merged, 0, mhalf);                                      // 0
    cudaMemsetAsync((char*)p_merged + mhalf, 0, mbytes - mhalf);              // 1
    zero_stats_kernel<<<1, 64>>>();                                           // 2
    transpose_nbr_kernel<<<tblocks, 256>>>(nbr, N);                           // 3
    fuse_t2_kernel<<<(N + 15) / 16, 256>>>(f2, Wobo, bobo, seg + N, N);       // 4
    conv_kernel<<<cblocks, 256>>>(vox, W0, (float*)p_y0, N, 0);               // 5 (profiled)
    bnrelu_kernel<<<(N * 4 + 255) / 256, 256>>>((const float*)p_y0,
                                                (float*)p_y0b, g0, b0,
                                                N, invN);                     // 6
    conv_kernel<<<cblocks, 256>>>((const float*)p_y0b, W1,
                                  (float*)p_y1, N, 32);                       // 7
    fuse_h_kernel<<<(N + 15) / 16, 256>>>((const float*)p_y1, g1, b1,
                                          seg, N, invN);                      // 8
    out_kernel<<<(U + 31) / 32, 256>>>(Wf, bf, (float*)d_out, U);             // 9
}

// round 10
// speedup vs baseline: 1.0012x; 1.0012x over previous
#include <cuda_runtime.h>

#define CEPS 1e-3f
#define NPMAX 100352

// scratch (allocation-free rule: __device__ globals)
__device__ float g_y0[NPMAX * 16];
__device__ float g_y0b[NPMAX * 16];
__device__ float g_y1[NPMAX * 16];
__device__ float g_merged[200000 * 16];
__device__ float g_stats[64];     // [0:16) sum0, [16:32) sq0, [32:48) sum1, [48:64) sq1
__device__ int   g_nbrT[27 * NPMAX];   // permuted, k-major
__device__ int   g_rowof[NPMAX];       // i -> original row n
__device__ int   g_cls[NPMAX];
__device__ int   g_blkcnt[512 * 8];
__device__ int   g_blkbase[512 * 8];
__device__ int   g_clsoff[8];

// ---------------------------------------------------------------------------
// Pass 1: per-row parity class (from validity of +x/+y/+z neighbors) and
// per-(block,class) counts.
// ---------------------------------------------------------------------------
__global__ __launch_bounds__(256) void count_kernel(
    const int* __restrict__ nbr, int N)
{
    __shared__ int cnt[8];
    int tid = threadIdx.x;
    if (tid < 8) cnt[tid] = 0;
    __syncthreads();
    int n = blockIdx.x * 256 + tid;
    if (n < N) {
        int cls = ((nbr[n * 27 + 14] >= 0) ? 4 : 0)
                | ((nbr[n * 27 + 16] >= 0) ? 2 : 0)
                | ((nbr[n * 27 + 22] >= 0) ? 1 : 0);
        g_cls[n] = cls;
        atomicAdd(&cnt[cls], 1);
    }
    __syncthreads();
    if (tid < 8) g_blkcnt[blockIdx.x * 8 + tid] = cnt[tid];
}

// Pass 2: two-level prefix (lane = class), relative block bases + class offsets.
__global__ void prefix_kernel(int nblk)
{
    int lane = threadIdx.x;
    if (lane >= 8) return;
    int run = 0;
    for (int b = 0; b < nblk; b++) {
        int c = g_blkcnt[b * 8 + lane];
        g_blkbase[b * 8 + lane] = run;
        run += c;
    }
    int off = 0;
    for (int j = 0; j < 8; j++) {
        int v = __shfl_sync(0xffu, run, j);
        if (j < lane) off += v;
    }
    g_clsoff[lane] = off;
}

// Pass 3: permuted k-major rulebook + row map.
__global__ __launch_bounds__(256) void build_kernel(
    const int* __restrict__ nbr, int N, int NP)
{
    __shared__ int snbr[256 * 27];
    __shared__ int base[8];
    int tid = threadIdx.x;
    int n0 = blockIdx.x * 256;
    int lim = (N - n0) * 27;
    for (int i = tid; i < 256 * 27; i += 256)
        snbr[i] = (i < lim) ? nbr[n0 * 27 + i] : -1;
    if (tid < 8) base[tid] = g_clsoff[tid] + g_blkbase[blockIdx.x * 8 + tid];
    __syncthreads();
    int n = n0 + tid;
    if (n < N) {
        int pos = atomicAdd(&base[g_cls[n]], 1);
        g_rowof[pos] = n;
#pragma unroll
        for (int k = 0; k < 27; k++)
            g_nbrT[k * NP + pos] = snbr[tid * 27 + k];
    }
}

// ---------------------------------------------------------------------------
// Submanifold 3x3x3 conv over class-sorted rows. Thread = one (permuted) row,
// all 16 couts. Warp = same-parity rows -> the __any skip eliminates ~2/3 of
// the 27 offsets (load AND 256-FMA block).
// ---------------------------------------------------------------------------
__global__ __launch_bounds__(128) void conv_kernel(
    const float* __restrict__ x, const float* __restrict__ W,
    float* __restrict__ y, int N, int NP, int statbase)
{
    __shared__ float Ws[27 * 256];   // 27.6 KB [k][c][o]
    __shared__ float sstat[32];

    int tid = threadIdx.x;
    for (int i = tid; i < 27 * 256; i += 128) Ws[i] = W[i];
    if (tid < 32) sstat[tid] = 0.f;
    __syncthreads();

    int i  = blockIdx.x * 128 + tid;
    bool vn = (i < N);
    int nrow = vn ? g_rowof[i] : 0;

    float4 a0 = make_float4(0.f, 0.f, 0.f, 0.f);
    float4 a1 = a0, a2 = a0, a3 = a0;

#define CSTEP(xc, cidx) {                                          \
        const float4* wp = (const float4*)(Wk + (cidx) * 16);      \
        float4 w0 = wp[0], w1 = wp[1], w2 = wp[2], w3 = wp[3];     \
        a0.x = fmaf(xc, w0.x, a0.x); a0.y = fmaf(xc, w0.y, a0.y);  \
        a0.z = fmaf(xc, w0.z, a0.z); a0.w = fmaf(xc, w0.w, a0.w);  \
        a1.x = fmaf(xc, w1.x, a1.x); a1.y = fmaf(xc, w1.y, a1.y);  \
        a1.z = fmaf(xc, w1.z, a1.z); a1.w = fmaf(xc, w1.w, a1.w);  \
        a2.x = fmaf(xc, w2.x, a2.x); a2.y = fmaf(xc, w2.y, a2.y);  \
        a2.z = fmaf(xc, w2.z, a2.z); a2.w = fmaf(xc, w2.w, a2.w);  \
        a3.x = fmaf(xc, w3.x, a3.x); a3.y = fmaf(xc, w3.y, a3.y);  \
        a3.z = fmaf(xc, w3.z, a3.z); a3.w = fmaf(xc, w3.w, a3.w);  }

    for (int k = 0; k < 27; k++) {
        int id = vn ? g_nbrT[k * NP + i] : -1;
        if (!__any_sync(0xffffffffu, id >= 0)) continue;

        float4 v0, v1, v2, v3;
        if (id >= 0) {
            const float4* xp = (const float4*)(x + id * 16);
            v0 = xp[0]; v1 = xp[1]; v2 = xp[2]; v3 = xp[3];
        } else {
            v0 = v1 = v2 = v3 = make_float4(0.f, 0.f, 0.f, 0.f);
        }
        const float* Wk = Ws + k * 256;
        CSTEP(v0.x, 0)  CSTEP(v0.y, 1)  CSTEP(v0.z, 2)  CSTEP(v0.w, 3)
        CSTEP(v1.x, 4)  CSTEP(v1.y, 5)  CSTEP(v1.z, 6)  CSTEP(v1.w, 7)
        CSTEP(v2.x, 8)  CSTEP(v2.y, 9)  CSTEP(v2.z, 10) CSTEP(v2.w, 11)
        CSTEP(v3.x, 12) CSTEP(v3.y, 13) CSTEP(v3.z, 14) CSTEP(v3.w, 15)
    }
#undef CSTEP

    if (vn) {
        float4* yp = (float4*)(y + nrow * 16);
        yp[0] = a0; yp[1] = a1; yp[2] = a2; yp[3] = a3;
    }

    // ---- BN stats: per-channel butterfly, lane0 -> SMEM, block -> global ----
    float av[16] = {a0.x, a0.y, a0.z, a0.w, a1.x, a1.y, a1.z, a1.w,
                    a2.x, a2.y, a2.z, a2.w, a3.x, a3.y, a3.z, a3.w};
#pragma unroll
    for (int c = 0; c < 16; c++) {
        float s = av[c];
        float q = s * s;
#pragma unroll
        for (int off = 1; off < 32; off <<= 1) {
            s += __shfl_xor_sync(0xffffffffu, s, off);
            q += __shfl_xor_sync(0xffffffffu, q, off);
        }
        if ((tid & 31) == 0) {
            atomicAdd(&sstat[c], s);
            atomicAdd(&sstat[16 + c], q);
        }
    }
    __syncthreads();
    if (tid < 32) atomicAdd(&g_stats[statbase + tid], sstat[tid]);
}

// y0b = relu(bn0(y0)) elementwise (affine from g_stats base 0)
__global__ __launch_bounds__(256) void bnrelu_kernel(
    const float* __restrict__ yin, float* __restrict__ yout,
    const float* __restrict__ g, const float* __restrict__ b,
    int N, float invN)
{
    __shared__ float saff[32];
    int tid = threadIdx.x;
    if (tid < 16) {
        float mu  = g_stats[tid] * invN;
        float var = g_stats[16 + tid] * invN - mu * mu;
        float s   = g[tid] * rsqrtf(var + CEPS);
        saff[tid]      = s;
        saff[16 + tid] = b[tid] - mu * s;
    }
    __syncthreads();
    int i = blockIdx.x * 256 + tid;      // one float4 (4 channels) per thread
    if (i >= N * 4) return;
    int c4 = (i & 3) * 4;
    float4 v = *(const float4*)(yin + i * 4);
    v.x = fmaxf(fmaf(v.x, saff[c4 + 0], saff[16 + c4 + 0]), 0.f);
    v.y = fmaxf(fmaf(v.y, saff[c4 + 1], saff[16 + c4 + 1]), 0.f);
    v.z = fmaxf(fmaf(v.z, saff[c4 + 2], saff[16 + c4 + 2]), 0.f);
    v.w = fmaxf(fmaf(v.w, saff[c4 + 3], saff[16 + c4 + 3]), 0.f);
    *(float4*)(yout + i * 4) = v;
}

// tiny stats-zero kernel
__global__ void zero_stats_kernel() {
    if (threadIdx.x < 64) g_stats[threadIdx.x] = 0.f;
}

// t2 = f2 @ Wobo + bobo, atomicAdd-scatter into merged
__global__ __launch_bounds__(256) void fuse_t2_kernel(
    const float* __restrict__ f2, const float* __restrict__ Wobo,
    const float* __restrict__ bobo, const int* __restrict__ seg2, int N)
{
    __shared__ float Wo[256];
    __shared__ float sf[16 * 17];
    __shared__ float sb[16];
    int tid = threadIdx.x;
    Wo[tid] = Wobo[tid];
    if (tid < 16) sb[tid] = bobo[tid];
    int n0 = blockIdx.x * 16;
    if (tid < 64) {
        int r = tid >> 2, c4 = (tid & 3) * 4;
        float4 v = make_float4(0.f, 0.f, 0.f, 0.f);
        if (n0 + r < N) v = *(const float4*)(f2 + (n0 + r) * 16 + c4);
        sf[r * 17 + c4 + 0] = v.x; sf[r * 17 + c4 + 1] = v.y;
        sf[r * 17 + c4 + 2] = v.z; sf[r * 17 + c4 + 3] = v.w;
    }
    __syncthreads();
    int tx = tid & 15, ty = tid >> 4;
    int n = n0 + ty;
    if (n >= N) return;
    float acc = sb[tx];
#pragma unroll
    for (int c = 0; c < 16; c++)
        acc = fmaf(sf[ty * 17 + c], Wo[c * 16 + tx], acc);
    atomicAdd(&g_merged[seg2[n] * 16 + tx], acc);
}

// h = relu(bn1(y1)), atomicAdd-scatter into merged
__global__ __launch_bounds__(256) void fuse_h_kernel(
    const float* __restrict__ y1, const float* __restrict__ g1,
    const float* __restrict__ b1, const int* __restrict__ seg, int N, float invN)
{
    __shared__ float saff[32];
    int tid = threadIdx.x;
    if (tid < 16) {
        float mu  = g_stats[32 + tid] * invN;
        float var = g_stats[48 + tid] * invN - mu * mu;
        float s   = g1[tid] * rsqrtf(var + CEPS);
        saff[tid]      = s;
        saff[16 + tid] = b1[tid] - mu * s;
    }
    __syncthreads();
    int tx = tid & 15, ty = tid >> 4;
    int n = blockIdx.x * 16 + ty;
    if (n >= N) return;
    float h = fmaxf(fmaf(y1[n * 16 + tx], saff[tx], saff[16 + tx]), 0.f);
    atomicAdd(&g_merged[seg[n] * 16 + tx], h);
}

// out[u,:] = merged[u,:] @ Wf + bf.  32 rows x 128 cols per block.
__global__ __launch_bounds__(256) void out_kernel(
    const float* __restrict__ Wf, const float* __restrict__ bf,
    float* __restrict__ out, int U)
{
    __shared__ float Wfs[2048];
    __shared__ float sx[32 * 16];
    int tid = threadIdx.x;
    for (int i = tid; i < 2048; i += 256) Wfs[i] = Wf[i];
    int u0 = blockIdx.x * 32;
    if (tid < 128) {
        int r = tid >> 2, c4 = (tid & 3) * 4;
        float4 v = make_float4(0.f, 0.f, 0.f, 0.f);
        if (u0 + r < U) v = *(const float4*)(g_merged + (u0 + r) * 16 + c4);
        *(float4*)(sx + r * 16 + c4) = v;
    }
    __syncthreads();

    int cx = tid & 31, ry = tid >> 5;
    float4 bv = *(const float4*)(bf + cx * 4);
    float4 a0 = bv, a1 = bv, a2 = bv, a3 = bv;

#pragma unroll
    for (int c = 0; c < 16; c++) {
        float4 wv = *(const float4*)(Wfs + c * 128 + cx * 4);
        float x0 = sx[(ry * 4 + 0) * 16 + c];
        float x1 = sx[(ry * 4 + 1) * 16 + c];
        float x2 = sx[(ry * 4 + 2) * 16 + c];
        float x3 = sx[(ry * 4 + 3) * 16 + c];
        a0.x = fmaf(x0, wv.x, a0.x); a0.y = fmaf(x0, wv.y, a0.y);
        a0.z = fmaf(x0, wv.z, a0.z); a0.w = fmaf(x0, wv.w, a0.w);
        a1.x = fmaf(x1, wv.x, a1.x); a1.y = fmaf(x1, wv.y, a1.y);
        a1.z = fmaf(x1, wv.z, a1.z); a1.w = fmaf(x1, wv.w, a1.w);
        a2.x = fmaf(x2, wv.x, a2.x); a2.y = fmaf(x2, wv.y, a2.y);
        a2.z = fmaf(x2, wv.z, a2.z); a2.w = fmaf(x2, wv.w, a2.w);
        a3.x = fmaf(x3, wv.x, a3.x); a3.y = fmaf(x3, wv.y, a3.y);
        a3.z = fmaf(x3, wv.z, a3.z); a3.w = fmaf(x3, wv.w, a3.w);
    }

    int u = u0 + ry * 4;
    if (u + 0 < U) *(float4*)(out + (u + 0) * 128 + cx * 4) = a0;
    if (u + 1 < U) *(float4*)(out + (u + 1) * 128 + cx * 4) = a1;
    if (u + 2 < U) *(float4*)(out + (u + 2) * 128 + cx * 4) = a2;
    if (u + 3 < U) *(float4*)(out + (u + 3) * 128 + cx * 4) = a3;
}

extern "C" void kernel_launch(void* const* d_in, const int* in_sizes, int n_in,
                              void* d_out, int out_size)
{
    const float* vox  = (const float*)d_in[0];
    const float* f2   = (const float*)d_in[1];
    const float* W0   = (const float*)d_in[2];
    const float* g0   = (const float*)d_in[3];
    const float* b0   = (const float*)d_in[4];
    const float* W1   = (const float*)d_in[5];
    const float* g1   = (const float*)d_in[6];
    const float* b1   = (const float*)d_in[7];
    const float* Wobo = (const float*)d_in[8];
    const float* bobo = (const float*)d_in[9];
    const float* Wf   = (const float*)d_in[10];
    const float* bf   = (const float*)d_in[11];
    const int*   nbr  = (const int*)d_in[12];
    const int*   seg  = (const int*)d_in[13];

    int N  = in_sizes[0] / 16;
    int U  = out_size / 128;
    int NP = (N + 255) & ~255;

    void *p_merged, *p_y0, *p_y0b, *p_y1;
    cudaGetSymbolAddress(&p_merged, g_merged);
    cudaGetSymbolAddress(&p_y0,     g_y0);
    cudaGetSymbolAddress(&p_y0b,    g_y0b);
    cudaGetSymbolAddress(&p_y1,     g_y1);

    float invN = 1.0f / (float)N;
    int nblk = (N + 255) / 256;
    int cblocks = (N + 127) / 128;

    // launch indices (ncu -s 5 -c 1 profiles index 5 = conv0)
    cudaMemsetAsync(p_merged, 0, (size_t)U * 16 * sizeof(float));             // 0
    zero_stats_kernel<<<1, 64>>>();                                           // 1
    count_kernel<<<nblk, 256>>>(nbr, N);                                      // 2
    prefix_kernel<<<1, 32>>>(nblk);                                           // 3
    build_kernel<<<nblk, 256>>>(nbr, N, NP);                                  // 4
    conv_kernel<<<cblocks, 128>>>(vox, W0, (float*)p_y0, N, NP, 0);           // 5 (profiled)
    bnrelu_kernel<<<(N * 4 + 255) / 256, 256>>>((const float*)p_y0,
                                                (float*)p_y0b, g0, b0,
                                                N, invN);                     // 6
    conv_kernel<<<cblocks, 128>>>((const float*)p_y0b, W1,
                                  (float*)p_y1, N, NP, 32);                   // 7
    fuse_h_kernel<<<(N + 15) / 16, 256>>>((const float*)p_y1, g1, b1,
                                          seg, N, invN);                      // 8
    fuse_t2_kernel<<<(N + 15) / 16, 256>>>(f2, Wobo, bobo, seg + N, N);       // 9
    out_kernel<<<(U + 31) / 32, 256>>>(Wf, bf, (float*)d_out, U);             // 10
}